// round 4
// baseline (speedup 1.0000x reference)
#include <cuda_runtime.h>
#include <cstdint>

// ---------------- problem constants ----------------
#define MM   8192
#define NN   2048
#define KIN  2048
#define KK   4096
#define NELEM_GRID ((double)KIN*NN*8)

// ---------------- GEMM tiling ----------------
#define BM 128
#define BN 256
#define BK 16                 // K per stage (floats)
#define ASTR 20               // padded row stride (floats): conflict-free LDSM
#define NSTAGE 5
#define NT (KK / BK)          // 256

#define ABYTES (BM * ASTR * 4)               // 10240
#define BBYTES (BN * ASTR * 4)               // 20480
#define AOFF(s) ((s) * ABYTES)
#define BOFF(s) (NSTAGE * ABYTES + (s) * BBYTES)
#define SMEM_TOTAL (NSTAGE * (ABYTES + BBYTES))   // 153600

// ---------------- device scratch ----------------
__device__ float g_A[(size_t)MM * KK];     // [M][K]: [x | basis], tf32-rounded
__device__ float g_B[(size_t)NN * KK];     // [N][K]: [Wb | W2^T], tf32-rounded
__device__ unsigned long long g_meanacc;   // fixed-point (2^-32) grid sum

// ---------------- helpers ----------------
__device__ __forceinline__ float tf32r(float f) {
    uint32_t u;
    asm("cvt.rna.tf32.f32 %0, %1;" : "=r"(u) : "f"(f));
    return __uint_as_float(u);
}

__device__ __forceinline__ void cp16(uint32_t smem, const void* gmem) {
    asm volatile("cp.async.cg.shared.global [%0], [%1], 16;" :: "r"(smem), "l"(gmem));
}

__device__ __forceinline__ void ldsm4(uint32_t* r, uint32_t addr) {
    asm volatile("ldmatrix.sync.aligned.m8n8.x4.shared.b16 {%0,%1,%2,%3}, [%4];"
                 : "=r"(r[0]), "=r"(r[1]), "=r"(r[2]), "=r"(r[3]) : "r"(addr));
}

__device__ __forceinline__ void mma_tf32(float* d, const uint32_t* a, const uint32_t* b) {
    asm volatile(
        "mma.sync.aligned.m16n8k8.row.col.f32.tf32.tf32.f32 "
        "{%0,%1,%2,%3}, {%4,%5,%6,%7}, {%8,%9}, {%0,%1,%2,%3};"
        : "+f"(d[0]), "+f"(d[1]), "+f"(d[2]), "+f"(d[3])
        : "r"(a[0]), "r"(a[1]), "r"(a[2]), "r"(a[3]), "r"(b[0]), "r"(b[1]));
}

// ======================= prep 1: grid reduce + transpose + mean ===========
// g_B[o][2048+i] = tf32( sum_g grid[i][o][g] );  deterministic fixed-point
// atomic accumulation of the global sum for the mean.
__global__ void k_gridsum(const float* __restrict__ grid) {
    __shared__ float tile[32][33];
    __shared__ float red[256];
    int i0 = blockIdx.x * 32, o0 = blockIdx.y * 32;
    int tx = threadIdx.x & 31, ty = threadIdx.x >> 5;   // 32 x 8
    const float4* g4 = reinterpret_cast<const float4*>(grid);
    float loc = 0.f;
    #pragma unroll
    for (int r = ty; r < 32; r += 8) {
        size_t idx8 = (size_t)(i0 + r) * NN + (o0 + tx);
        float4 p = g4[idx8 * 2];
        float4 q = g4[idx8 * 2 + 1];
        float s = ((p.x + p.y) + (p.z + p.w)) + ((q.x + q.y) + (q.z + q.w));
        tile[r][tx] = s;
        loc += s;
    }
    red[threadIdx.x] = loc;
    __syncthreads();
    #pragma unroll
    for (int r = ty; r < 32; r += 8)
        g_B[(size_t)(o0 + r) * KK + KIN + i0 + tx] = tf32r(tile[tx][r]);
    for (int off = 128; off > 0; off >>= 1) {
        if (threadIdx.x < off) red[threadIdx.x] += red[threadIdx.x + off];
        __syncthreads();
    }
    if (threadIdx.x == 0) {
        long long q = llrint((double)red[0] * 4294967296.0);
        atomicAdd(&g_meanacc, (unsigned long long)q);
    }
}

// ======================= prep 2: round Wb into B[N][0:2048] ===============
__global__ void k_roundWb(const float* __restrict__ bw) {
    int t = blockIdx.x * 256 + threadIdx.x;      // one float4
    int n = t >> 9, k4 = t & 511;
    const float4* s4 = reinterpret_cast<const float4*>(bw);
    float4 v = s4[(size_t)t];
    float4 r;
    r.x = tf32r(v.x); r.y = tf32r(v.y); r.z = tf32r(v.z); r.w = tf32r(v.w);
    reinterpret_cast<float4*>(g_B)[(size_t)n * (KK / 4) + k4] = r;
}

// ======================= prep 3: build A = [x | basis] ====================
__global__ void k_buildA(const float* __restrict__ x) {
    int t = blockIdx.x * 256 + threadIdx.x;
    int b = t >> 9, c4 = t & 511;
    const float4* x4 = reinterpret_cast<const float4*>(x);
    float4 v = x4[(size_t)b * 512 + c4];
    double acc = (double)(long long)g_meanacc;
    float m = (float)(acc * (1.0 / 4294967296.0) / NELEM_GRID);
    float4* A4 = reinterpret_cast<float4*>(g_A);
    float4 xv;
    xv.x = tf32r(v.x); xv.y = tf32r(v.y); xv.z = tf32r(v.z); xv.w = tf32r(v.w);
    A4[(size_t)b * (KK / 4) + c4] = xv;
    float dx = v.x - m, dy = v.y - m, dz = v.z - m, dw = v.w - m;
    float4 e;
    e.x = tf32r(__expf(-dx * dx));
    e.y = tf32r(__expf(-dy * dy));
    e.z = tf32r(__expf(-dz * dz));
    e.w = tf32r(__expf(-dw * dw));
    A4[(size_t)b * (KK / 4) + (KIN / 4) + c4] = e;
}

// ======================= main GEMM: 128x256x16, ldmatrix + mma.sync =======
__global__ __launch_bounds__(256, 1) void k_gemm(float* __restrict__ out) {
    extern __shared__ char smc[];
    uint32_t sb = (uint32_t)__cvta_generic_to_shared(smc);

    // reset the mean accumulator for the next replay of this graph
    if (blockIdx.x == 0 && blockIdx.y == 0 && threadIdx.x == 0) g_meanacc = 0ULL;

    int tid  = threadIdx.x;
    int warp = tid >> 5, lane = tid & 31;
    int wm = warp & 1;         // 2 warps along M -> 64 rows each
    int wn = warp >> 1;        // 4 warps along N -> 64 cols each
    int g  = lane >> 2;        // 0..7
    int tg = lane & 3;         // 0..3
    int m0 = blockIdx.y * BM;
    int n0 = blockIdx.x * BN;

    // ldmatrix lane address offsets (bytes within a stage)
    int li = lane >> 3;        // matrix id 0..3
    int lr = lane & 7;         // row within matrix
    uint32_t a_base = ((wm * 64 + (li & 1) * 8 + lr) * ASTR + (li >> 1) * 4) * 4;
    uint32_t b_base = ((wn * 64 + (li >> 1) * 8 + lr) * ASTR + (li & 1) * 4) * 4;

    // cp.async mapping: A 512 chunks (2/thr), B 1024 chunks (4/thr)
    int r0 = tid >> 2;               // 0..63
    int kc = tid & 3;                // 16B k-chunk
    const float* Ag0 = g_A + (size_t)(m0 + r0)      * KK + kc * 4;
    const float* Ag1 = g_A + (size_t)(m0 + r0 + 64) * KK + kc * 4;
    const float* Bg0 = g_B + (size_t)(n0 + r0)       * KK + kc * 4;
    const float* Bg1 = g_B + (size_t)(n0 + r0 + 64)  * KK + kc * 4;
    const float* Bg2 = g_B + (size_t)(n0 + r0 + 128) * KK + kc * 4;
    const float* Bg3 = g_B + (size_t)(n0 + r0 + 192) * KK + kc * 4;
    uint32_t da0 = r0 * (ASTR * 4) + kc * 16;
    uint32_t da1 = da0 + 64  * (ASTR * 4);
    uint32_t db0 = da0;
    uint32_t db1 = da0 + 64  * (ASTR * 4);
    uint32_t db2 = da0 + 128 * (ASTR * 4);
    uint32_t db3 = da0 + 192 * (ASTR * 4);

    float acc[4][8][4];
    #pragma unroll
    for (int i = 0; i < 4; i++)
        #pragma unroll
        for (int j = 0; j < 8; j++)
            #pragma unroll
            for (int k = 0; k < 4; k++) acc[i][j][k] = 0.f;

    // prologue: stages 0..3
    #pragma unroll
    for (int s = 0; s < NSTAGE - 1; ++s) {
        int k0 = s * BK;
        cp16(sb + AOFF(s) + da0, Ag0 + k0);
        cp16(sb + AOFF(s) + da1, Ag1 + k0);
        cp16(sb + BOFF(s) + db0, Bg0 + k0);
        cp16(sb + BOFF(s) + db1, Bg1 + k0);
        cp16(sb + BOFF(s) + db2, Bg2 + k0);
        cp16(sb + BOFF(s) + db3, Bg3 + k0);
        asm volatile("cp.async.commit_group;");
    }

    int buf = 0;                 // stage being consumed
    int pf  = NSTAGE - 1;        // stage being prefetched
    #pragma unroll 1
    for (int kt = 0; kt < NT; ++kt) {
        asm volatile("cp.async.wait_group %0;" :: "n"(NSTAGE - 2));
        __syncthreads();

        if (kt + NSTAGE - 1 < NT) {
            int k0 = (kt + NSTAGE - 1) * BK;
            cp16(sb + AOFF(pf) + da0, Ag0 + k0);
            cp16(sb + AOFF(pf) + da1, Ag1 + k0);
            cp16(sb + BOFF(pf) + db0, Bg0 + k0);
            cp16(sb + BOFF(pf) + db1, Bg1 + k0);
            cp16(sb + BOFF(pf) + db2, Bg2 + k0);
            cp16(sb + BOFF(pf) + db3, Bg3 + k0);
        }
        asm volatile("cp.async.commit_group;");

        uint32_t abase = sb + AOFF(buf) + a_base;
        uint32_t bbase = sb + BOFF(buf) + b_base;

        // A fragments for both k8 slices (double-buffered in regs)
        uint32_t af[2][4][4];
        #pragma unroll
        for (int kb = 0; kb < 2; ++kb)
            #pragma unroll
            for (int mf = 0; mf < 4; ++mf)
                ldsm4(af[kb][mf], abase + kb * 32 + mf * (16 * ASTR * 4));

        #pragma unroll
        for (int kb = 0; kb < 2; ++kb) {
            #pragma unroll
            for (int nf2 = 0; nf2 < 4; ++nf2) {
                uint32_t bt[4];
                ldsm4(bt, bbase + kb * 32 + nf2 * (16 * ASTR * 4));
                uint32_t bA[2] = {bt[0], bt[1]};
                uint32_t bB[2] = {bt[2], bt[3]};
                #pragma unroll
                for (int mf = 0; mf < 4; ++mf) {
                    mma_tf32(acc[mf][nf2 * 2 + 0], af[kb][mf], bA);
                    mma_tf32(acc[mf][nf2 * 2 + 1], af[kb][mf], bB);
                }
            }
        }

        if (++buf == NSTAGE) buf = 0;
        if (++pf  == NSTAGE) pf  = 0;
        __syncthreads();
    }

    // epilogue
    #pragma unroll
    for (int mf = 0; mf < 4; ++mf) {
        #pragma unroll
        for (int nf = 0; nf < 8; ++nf) {
            int row0 = m0 + wm * 64 + mf * 16 + g;
            int col  = n0 + wn * 64 + nf * 8 + tg * 2;
            float2 v0 = make_float2(acc[mf][nf][0], acc[mf][nf][1]);
            float2 v1 = make_float2(acc[mf][nf][2], acc[mf][nf][3]);
            *reinterpret_cast<float2*>(&out[(size_t)row0 * NN + col])       = v0;
            *reinterpret_cast<float2*>(&out[(size_t)(row0 + 8) * NN + col]) = v1;
        }
    }
}

// ============================= launch =====================================
extern "C" void kernel_launch(void* const* d_in, const int* in_sizes, int n_in,
                              void* d_out, int out_size) {
    const float* x    = (const float*)d_in[0];   // (8192, 2048)
    const float* bw   = (const float*)d_in[1];   // (2048, 2048)
    const float* grid = (const float*)d_in[2];   // (2048, 2048, 8)
    float* out = (float*)d_out;                  // (8192, 2048)

    cudaFuncSetAttribute(k_gemm, cudaFuncAttributeMaxDynamicSharedMemorySize, SMEM_TOTAL);

    k_gridsum<<<dim3(KIN / 32, NN / 32), 256>>>(grid);
    k_roundWb<<<(NN * KIN / 4) / 256, 256>>>(bw);
    k_buildA<<<(MM * KIN / 4) / 256, 256>>>(x);
    k_gemm<<<dim3(NN / BN, MM / BM), 256, SMEM_TOTAL>>>(out);
}

// round 5
// speedup vs baseline: 1.8563x; 1.8563x over previous
#include <cuda_runtime.h>
#include <cuda_fp16.h>
#include <cstdint>

// ---------------- problem constants ----------------
#define MM   8192
#define NN   2048
#define KIN  2048
#define KK   4096
#define NELEM_GRID ((double)KIN*NN*8)

// ---------------- GEMM tiling (fp16 operands, fp32 accum) -----------------
#define BM 128
#define BN 128
#define KTILE 32              // K halves per stage
#define ASTR 40               // padded row stride in halves (80 B, 16B-aligned, conflict-free)
#define NSTAGE 4
#define NT (KK / KTILE)       // 128

#define ABYTES (BM * ASTR * 2)               // 10240
#define BBYTES (BN * ASTR * 2)               // 10240
#define AOFF(s) ((s) * ABYTES)
#define BOFF(s) (NSTAGE * ABYTES + (s) * BBYTES)
#define SMEM_TOTAL (NSTAGE * (ABYTES + BBYTES))   // 81920  -> 2 CTAs/SM

// ---------------- device scratch ----------------
__device__ __half g_A[(size_t)MM * KK];    // [M][K]: [x | basis]
__device__ __half g_B[(size_t)NN * KK];    // [N][K]: [Wb | W2^T]
__device__ unsigned long long g_meanacc;   // fixed-point (2^-32) grid sum

// ---------------- helpers ----------------
__device__ __forceinline__ void cp16(uint32_t smem, const void* gmem) {
    asm volatile("cp.async.cg.shared.global [%0], [%1], 16;" :: "r"(smem), "l"(gmem));
}

__device__ __forceinline__ void ldsm4(uint32_t* r, uint32_t addr) {
    asm volatile("ldmatrix.sync.aligned.m8n8.x4.shared.b16 {%0,%1,%2,%3}, [%4];"
                 : "=r"(r[0]), "=r"(r[1]), "=r"(r[2]), "=r"(r[3]) : "r"(addr));
}

__device__ __forceinline__ void mma_f16(float* d, const uint32_t* a, const uint32_t* b) {
    asm volatile(
        "mma.sync.aligned.m16n8k16.row.col.f32.f16.f16.f32 "
        "{%0,%1,%2,%3}, {%4,%5,%6,%7}, {%8,%9}, {%0,%1,%2,%3};"
        : "+f"(d[0]), "+f"(d[1]), "+f"(d[2]), "+f"(d[3])
        : "r"(a[0]), "r"(a[1]), "r"(a[2]), "r"(a[3]), "r"(b[0]), "r"(b[1]));
}

// ======================= prep 1: grid reduce + transpose + mean ===========
// g_B[o][2048+i] = half( sum_g grid[i][o][g] ); deterministic fixed-point mean acc.
__global__ void k_gridsum(const float* __restrict__ grid) {
    __shared__ float tile[32][33];
    __shared__ float red[256];
    int i0 = blockIdx.x * 32, o0 = blockIdx.y * 32;
    int tx = threadIdx.x & 31, ty = threadIdx.x >> 5;   // 32 x 8
    const float4* g4 = reinterpret_cast<const float4*>(grid);
    float loc = 0.f;
    #pragma unroll
    for (int r = ty; r < 32; r += 8) {
        size_t idx8 = (size_t)(i0 + r) * NN + (o0 + tx);
        float4 p = g4[idx8 * 2];
        float4 q = g4[idx8 * 2 + 1];
        float s = ((p.x + p.y) + (p.z + p.w)) + ((q.x + q.y) + (q.z + q.w));
        tile[r][tx] = s;
        loc += s;
    }
    red[threadIdx.x] = loc;
    __syncthreads();
    #pragma unroll
    for (int r = ty; r < 32; r += 8)
        g_B[(size_t)(o0 + r) * KK + KIN + i0 + tx] = __float2half_rn(tile[tx][r]);
    for (int off = 128; off > 0; off >>= 1) {
        if (threadIdx.x < off) red[threadIdx.x] += red[threadIdx.x + off];
        __syncthreads();
    }
    if (threadIdx.x == 0) {
        long long q = llrint((double)red[0] * 4294967296.0);
        atomicAdd(&g_meanacc, (unsigned long long)q);
    }
}

// ======================= prep 2: Wb -> half B[N][0:2048] ==================
__global__ void k_roundWb(const float* __restrict__ bw) {
    int t = blockIdx.x * 256 + threadIdx.x;      // one float4
    int n = t >> 9, k4 = t & 511;
    const float4* s4 = reinterpret_cast<const float4*>(bw);
    float4 v = s4[(size_t)t];
    __half2* dst = reinterpret_cast<__half2*>(g_B) + (size_t)n * (KK / 2) + k4 * 2;
    dst[0] = __floats2half2_rn(v.x, v.y);
    dst[1] = __floats2half2_rn(v.z, v.w);
}

// ======================= prep 3: build A = [x | basis] (half) =============
__global__ void k_buildA(const float* __restrict__ x) {
    int t = blockIdx.x * 256 + threadIdx.x;
    int b = t >> 9, c4 = t & 511;
    const float4* x4 = reinterpret_cast<const float4*>(x);
    float4 v = x4[(size_t)b * 512 + c4];
    double acc = (double)(long long)g_meanacc;
    float m = (float)(acc * (1.0 / 4294967296.0) / NELEM_GRID);
    __half2* A2 = reinterpret_cast<__half2*>(g_A);
    size_t base = (size_t)b * (KK / 2) + c4 * 2;
    A2[base + 0] = __floats2half2_rn(v.x, v.y);
    A2[base + 1] = __floats2half2_rn(v.z, v.w);
    float dx = v.x - m, dy = v.y - m, dz = v.z - m, dw = v.w - m;
    size_t base2 = base + (KIN / 2);
    A2[base2 + 0] = __floats2half2_rn(__expf(-dx * dx), __expf(-dy * dy));
    A2[base2 + 1] = __floats2half2_rn(__expf(-dz * dz), __expf(-dw * dw));
}

// ======================= main GEMM: 128x128x32, fp16 mma.sync =============
__global__ __launch_bounds__(256, 2) void k_gemm(float* __restrict__ out) {
    extern __shared__ char smc[];
    uint32_t sb = (uint32_t)__cvta_generic_to_shared(smc);

    // reset mean accumulator for the next graph replay
    if (blockIdx.x == 0 && blockIdx.y == 0 && threadIdx.x == 0) g_meanacc = 0ULL;

    int tid  = threadIdx.x;
    int warp = tid >> 5, lane = tid & 31;
    int wm = warp & 3;         // 4 warps along M -> 32 rows each
    int wn = warp >> 2;        // 2 warps along N -> 64 cols each
    int g  = lane >> 2;        // 0..7
    int tg = lane & 3;         // 0..3
    int m0 = blockIdx.y * BM;
    int n0 = blockIdx.x * BN;

    // ldmatrix per-lane offsets (bytes, within one stage)
    int li = lane >> 3, lr = lane & 7;
    // A m16k16: mats (m0-7,k0)(m8-15,k0)(m0-7,k8)(m8-15,k8): row=lane&15, chunk=lane>>4
    uint32_t a_lane = (uint32_t)((lane & 15) * (ASTR * 2) + (lane >> 4) * 16);
    uint32_t a_warp = (uint32_t)(wm * 32 * (ASTR * 2));
    // B [n][k]: mats (n0-7,k0)(n0-7,k8)(n8-15,k0)(n8-15,k8)
    uint32_t b_lane = (uint32_t)((((li >> 1) * 8) + lr) * (ASTR * 2) + (li & 1) * 16);
    uint32_t b_warp = (uint32_t)(wn * 64 * (ASTR * 2));

    // cp.async mapping: per operand 512 16B-chunks, 2/thread
    int r0 = tid >> 1;                 // row 0..127
    int c0 = (tid & 1) * 2;            // chunk 0/2 (+1)
    const __half* Ag = g_A + (size_t)(m0 + r0) * KK + c0 * 8;
    const __half* Bg = g_B + (size_t)(n0 + r0) * KK + c0 * 8;
    uint32_t dA = (uint32_t)(r0 * (ASTR * 2) + c0 * 16);

    float acc[2][8][4];
    #pragma unroll
    for (int i = 0; i < 2; i++)
        #pragma unroll
        for (int j = 0; j < 8; j++)
            #pragma unroll
            for (int k = 0; k < 4; k++) acc[i][j][k] = 0.f;

    // prologue: stages 0..2
    #pragma unroll
    for (int s = 0; s < NSTAGE - 1; ++s) {
        int k0 = s * KTILE;
        cp16(sb + AOFF(s) + dA,      Ag + k0);
        cp16(sb + AOFF(s) + dA + 16, Ag + k0 + 8);
        cp16(sb + BOFF(s) + dA,      Bg + k0);
        cp16(sb + BOFF(s) + dA + 16, Bg + k0 + 8);
        asm volatile("cp.async.commit_group;");
    }

    #pragma unroll 1
    for (int kt = 0; kt < NT; ++kt) {
        asm volatile("cp.async.wait_group %0;" :: "n"(NSTAGE - 2));
        __syncthreads();

        if (kt + NSTAGE - 1 < NT) {
            int s  = (kt + NSTAGE - 1) & (NSTAGE - 1);
            int k0 = (kt + NSTAGE - 1) * KTILE;
            cp16(sb + AOFF(s) + dA,      Ag + k0);
            cp16(sb + AOFF(s) + dA + 16, Ag + k0 + 8);
            cp16(sb + BOFF(s) + dA,      Bg + k0);
            cp16(sb + BOFF(s) + dA + 16, Bg + k0 + 8);
        }
        asm volatile("cp.async.commit_group;");

        int buf = kt & (NSTAGE - 1);
        uint32_t abase = sb + AOFF(buf) + a_warp + a_lane;
        uint32_t bbase = sb + BOFF(buf) + b_warp + b_lane;

        #pragma unroll
        for (int s = 0; s < 2; ++s) {                 // two k16 slices
            uint32_t af[2][4];
            ldsm4(af[0], abase + s * 32);
            ldsm4(af[1], abase + s * 32 + 16 * (ASTR * 2));
            #pragma unroll
            for (int nf2 = 0; nf2 < 4; ++nf2) {       // 4 x (two n8 tiles)
                uint32_t bt[4];
                ldsm4(bt, bbase + s * 32 + nf2 * (16 * (ASTR * 2)));
                uint32_t b0[2] = {bt[0], bt[1]};
                uint32_t b1[2] = {bt[2], bt[3]};
                #pragma unroll
                for (int mf = 0; mf < 2; ++mf) {
                    mma_f16(acc[mf][nf2 * 2 + 0], af[mf], b0);
                    mma_f16(acc[mf][nf2 * 2 + 1], af[mf], b1);
                }
            }
        }
        __syncthreads();
    }

    // epilogue
    #pragma unroll
    for (int mf = 0; mf < 2; ++mf) {
        #pragma unroll
        for (int nf = 0; nf < 8; ++nf) {
            int row0 = m0 + wm * 32 + mf * 16 + g;
            int col  = n0 + wn * 64 + nf * 8 + tg * 2;
            float2 v0 = make_float2(acc[mf][nf][0], acc[mf][nf][1]);
            float2 v1 = make_float2(acc[mf][nf][2], acc[mf][nf][3]);
            *reinterpret_cast<float2*>(&out[(size_t)row0 * NN + col])       = v0;
            *reinterpret_cast<float2*>(&out[(size_t)(row0 + 8) * NN + col]) = v1;
        }
    }
}

// ============================= launch =====================================
extern "C" void kernel_launch(void* const* d_in, const int* in_sizes, int n_in,
                              void* d_out, int out_size) {
    const float* x    = (const float*)d_in[0];   // (8192, 2048)
    const float* bw   = (const float*)d_in[1];   // (2048, 2048)
    const float* grid = (const float*)d_in[2];   // (2048, 2048, 8)
    float* out = (float*)d_out;                  // (8192, 2048)

    cudaFuncSetAttribute(k_gemm, cudaFuncAttributeMaxDynamicSharedMemorySize, SMEM_TOTAL);

    k_gridsum<<<dim3(KIN / 32, NN / 32), 256>>>(grid);
    k_roundWb<<<(NN * KIN / 4) / 256, 256>>>(bw);
    k_buildA<<<(MM * KIN / 4) / 256, 256>>>(x);
    k_gemm<<<dim3(NN / BN, MM / BM), 256, SMEM_TOTAL>>>(out);
}